// round 5
// baseline (speedup 1.0000x reference)
#include <cuda_runtime.h>
#include <math.h>

#define B 32
#define H 512
#define E 256
#define VV 32000
#define TT 64
#define KF 768          // E + H (per-step feature length)
#define WOUT_LD 1280    // 2H + E
#define PADF 772        // KF + 4 pad -> conflict-free LDS.128
#define PADZ 516        // H + 4 pad

// ---------------- persistent device scratch (no allocations) ----------------
__device__ float d_scratch[TT * B * VV];        // logits in (T, B, V) layout
__device__ float d_base[B * VV];                // z @ W_out_z^T + b_out
__device__ float d_cg[4 * H * B];               // z @ W_ih_z^T + b_ih + b_hh, [R][b]
__device__ float d_hbuf[2][B * H];              // double-buffered hidden state
__device__ float d_cbuf[B * H];                 // cell state
__device__ unsigned long long d_slot[TT * B];   // packed (orderable(max) << 32) | ~argmax

__device__ __forceinline__ unsigned long long packmax(float f, int v) {
    unsigned u = __float_as_uint(f);
    u = (u & 0x80000000u) ? ~u : (u | 0x80000000u);   // order-preserving float->uint
    return ((unsigned long long)u << 32) | (unsigned)(~v);  // ties -> smallest v wins
}

__device__ __forceinline__ float sigmoidf_(float x) { return 1.0f / (1.0f + expf(-x)); }

// ---------------- init: h, c, argmax slots ----------------
__global__ void initK(const float* __restrict__ h0, const float* __restrict__ c0) {
    int i = blockIdx.x * blockDim.x + threadIdx.x;
    if (i < B * H) { d_hbuf[0][i] = h0[i]; d_cbuf[i] = c0[i]; }
    if (i < TT * B) d_slot[i] = 0ULL;
}

// ---------------- precompute gate constants: cg[R][b] = z[b].W_ih[R,:512] + b_ih + b_hh ----------------
__global__ void constgateK(const float* __restrict__ h0, const float* __restrict__ Wih,
                           const float* __restrict__ bih, const float* __restrict__ bhh) {
    int gw = (blockIdx.x * blockDim.x + threadIdx.x) >> 5;   // 65536 warps
    int lane = threadIdx.x & 31;
    int b = gw & 31;
    int R = gw >> 5;                                          // [0, 2048)
    const float* z = h0 + b * H;
    const float* w = Wih + (long)R * KF;                      // cols [0:512) multiply z
    float a = 0.f;
    for (int k = lane; k < H; k += 32) a += w[k] * z[k];
    #pragma unroll
    for (int o = 16; o > 0; o >>= 1) a += __shfl_down_sync(0xffffffffu, a, o);
    if (lane == 0) d_cg[R * B + b] = a + bih[R] + bhh[R];
}

// ---------------- precompute base[b][v] = z[b].W_out[v,:512] + b_out[v] ----------------
__global__ __launch_bounds__(256, 2) void baseK(const float* __restrict__ h0,
        const float* __restrict__ Wout, const float* __restrict__ bout) {
    extern __shared__ float zs[];   // B * PADZ floats
    int tid = threadIdx.x;
    for (int i = tid; i < B * H; i += 256) {
        int b = i >> 9, k = i & 511;
        zs[b * PADZ + k] = h0[i];
    }
    __syncthreads();
    int warp = tid >> 5, lane = tid & 31;
    int v0 = blockIdx.x * 64 + warp * 8;
    float4 acc[8];
    #pragma unroll
    for (int i = 0; i < 8; i++) acc[i] = make_float4(0.f, 0.f, 0.f, 0.f);
    const float4* fb = (const float4*)(zs + lane * PADZ);
    const float* wb = Wout + (long)v0 * WOUT_LD;              // cols [0:512)
    #pragma unroll 2
    for (int k = 0; k < H; k += 4) {
        float4 f = fb[k >> 2];
        #pragma unroll
        for (int i = 0; i < 8; i++) {
            float4 w = *(const float4*)(wb + (long)i * WOUT_LD + k);
            acc[i].x = fmaf(w.x, f.x, acc[i].x);
            acc[i].y = fmaf(w.y, f.y, acc[i].y);
            acc[i].z = fmaf(w.z, f.z, acc[i].z);
            acc[i].w = fmaf(w.w, f.w, acc[i].w);
        }
    }
    float out8[8];
    #pragma unroll
    for (int i = 0; i < 8; i++)
        out8[i] = (acc[i].x + acc[i].y) + (acc[i].z + acc[i].w) + bout[v0 + i];
    float* op = d_base + (long)lane * VV + v0;
    *(float4*)(op)     = make_float4(out8[0], out8[1], out8[2], out8[3]);
    *(float4*)(op + 4) = make_float4(out8[4], out8[5], out8[6], out8[7]);
}

// ---------------- per-step LSTM gates + pointwise update (warp per (b, j) quadruple) ----------------
__global__ __launch_bounds__(256) void gatesK(int t, const int* __restrict__ y0,
        const float* __restrict__ emb, const float* __restrict__ Wih,
        const float* __restrict__ Whh) {
    int gw = (blockIdx.x * blockDim.x + threadIdx.x) >> 5;    // 16384 warps
    int lane = threadIdx.x & 31;
    int b = gw & 31;
    int j = gw >> 5;                                          // [0, 512)
    int y = (t == 0) ? y0[b]
                     : (int)(~(unsigned)(d_slot[(t - 1) * B + b] & 0xFFFFFFFFull));
    const float* hold = d_hbuf[t & 1] + b * H;
    const float* ep   = emb + (long)y * E;
    const float* wi0 = Wih + (long)(0 * H + j) * KF + 512;    // e-part cols [512:768)
    const float* wi1 = Wih + (long)(1 * H + j) * KF + 512;
    const float* wi2 = Wih + (long)(2 * H + j) * KF + 512;
    const float* wi3 = Wih + (long)(3 * H + j) * KF + 512;
    const float* wh0 = Whh + (long)(0 * H + j) * H;
    const float* wh1 = Whh + (long)(1 * H + j) * H;
    const float* wh2 = Whh + (long)(2 * H + j) * H;
    const float* wh3 = Whh + (long)(3 * H + j) * H;
    float a0 = 0.f, a1 = 0.f, a2 = 0.f, a3 = 0.f;
    for (int k = lane; k < E; k += 32) {
        float f = ep[k];
        a0 = fmaf(wi0[k], f, a0); a1 = fmaf(wi1[k], f, a1);
        a2 = fmaf(wi2[k], f, a2); a3 = fmaf(wi3[k], f, a3);
    }
    for (int k = lane; k < H; k += 32) {
        float f = hold[k];
        a0 = fmaf(wh0[k], f, a0); a1 = fmaf(wh1[k], f, a1);
        a2 = fmaf(wh2[k], f, a2); a3 = fmaf(wh3[k], f, a3);
    }
    #pragma unroll
    for (int o = 16; o > 0; o >>= 1) {
        a0 += __shfl_down_sync(0xffffffffu, a0, o);
        a1 += __shfl_down_sync(0xffffffffu, a1, o);
        a2 += __shfl_down_sync(0xffffffffu, a2, o);
        a3 += __shfl_down_sync(0xffffffffu, a3, o);
    }
    if (lane == 0) {
        a0 += d_cg[(0 * H + j) * B + b];
        a1 += d_cg[(1 * H + j) * B + b];
        a2 += d_cg[(2 * H + j) * B + b];
        a3 += d_cg[(3 * H + j) * B + b];
        float ig = sigmoidf_(a0);
        float fg = sigmoidf_(a1);
        float gg = tanhf(a2);
        float og = sigmoidf_(a3);
        float c = fg * d_cbuf[b * H + j] + ig * gg;
        d_cbuf[b * H + j] = c;
        d_hbuf[(t + 1) & 1][b * H + j] = og * tanhf(c);
    }
}

// ---------------- per-step logits (K=768 part) + fused argmax ----------------
// lane = b; warp owns 8 v rows; W_out loads are warp-broadcast float4.
__global__ __launch_bounds__(256, 2) void logitsK(int t, const int* __restrict__ y0,
        const float* __restrict__ emb, const float* __restrict__ Wout) {
    extern __shared__ float fs[];                 // B * PADF floats (feat = [emb[y] | h_new])
    __shared__ int ys[B];
    __shared__ unsigned long long red[8][B];
    int tid = threadIdx.x;
    if (tid < B) {
        ys[tid] = (t == 0) ? y0[tid]
                           : (int)(~(unsigned)(d_slot[(t - 1) * B + tid] & 0xFFFFFFFFull));
    }
    __syncthreads();
    const float* hc = d_hbuf[(t + 1) & 1];        // h written by gatesK this step
    for (int i = tid; i < B * KF; i += 256) {
        int b = i / KF, k = i - b * KF;
        fs[b * PADF + k] = (k < E) ? emb[(long)ys[b] * E + k] : hc[b * H + (k - E)];
    }
    __syncthreads();
    int warp = tid >> 5, lane = tid & 31;
    int v0 = blockIdx.x * 64 + warp * 8;
    float4 acc[8];
    #pragma unroll
    for (int i = 0; i < 8; i++) acc[i] = make_float4(0.f, 0.f, 0.f, 0.f);
    const float4* fb = (const float4*)(fs + lane * PADF);
    const float* wb = Wout + (long)v0 * WOUT_LD + 512;        // cols [512:1280)
    #pragma unroll 2
    for (int k = 0; k < KF; k += 4) {
        float4 f = fb[k >> 2];
        #pragma unroll
        for (int i = 0; i < 8; i++) {
            float4 w = *(const float4*)(wb + (long)i * WOUT_LD + k);
            acc[i].x = fmaf(w.x, f.x, acc[i].x);
            acc[i].y = fmaf(w.y, f.y, acc[i].y);
            acc[i].z = fmaf(w.z, f.z, acc[i].z);
            acc[i].w = fmaf(w.w, f.w, acc[i].w);
        }
    }
    float out8[8];
    float best = __int_as_float(0xff800000);      // -inf
    int bestv = 0;
    const float* bp = d_base + (long)lane * VV + v0;
    #pragma unroll
    for (int i = 0; i < 8; i++) {
        float s = (acc[i].x + acc[i].y) + (acc[i].z + acc[i].w) + bp[i];
        out8[i] = s;
        if (s > best) { best = s; bestv = v0 + i; }   // strict > keeps first occurrence
    }
    float* sp = d_scratch + ((long)t * B + lane) * VV + v0;
    *(float4*)(sp)     = make_float4(out8[0], out8[1], out8[2], out8[3]);
    *(float4*)(sp + 4) = make_float4(out8[4], out8[5], out8[6], out8[7]);
    red[warp][lane] = packmax(best, bestv);
    __syncthreads();
    if (warp == 0) {
        unsigned long long m = red[0][lane];
        #pragma unroll
        for (int w = 1; w < 8; w++) { unsigned long long x = red[w][lane]; if (x > m) m = x; }
        atomicMax(&d_slot[t * B + lane], m);
    }
}

// ---------------- final transpose (T, B, V) -> (B, V, T) ----------------
__global__ void transposeK(float* __restrict__ out) {
    __shared__ float tile[32][33];
    int b  = blockIdx.z;
    int vt = blockIdx.x;     // V / 32 tiles
    int tt = blockIdx.y;     // T / 32 tiles
    int tx = threadIdx.x, ty = threadIdx.y;   // (32, 8)
    #pragma unroll
    for (int i = 0; i < 32; i += 8) {
        int t = tt * 32 + ty + i;
        int v = vt * 32 + tx;
        tile[ty + i][tx] = d_scratch[((long)t * B + b) * VV + v];
    }
    __syncthreads();
    #pragma unroll
    for (int i = 0; i < 32; i += 8) {
        int v = vt * 32 + ty + i;
        int t = tt * 32 + tx;
        out[((long)b * VV + v) * TT + t] = tile[tx][ty + i];
    }
}

// ---------------- launch ----------------
extern "C" void kernel_launch(void* const* d_in, const int* in_sizes, int n_in,
                              void* d_out, int out_size) {
    const int*   y0   = (const int*)d_in[0];
    const float* h0   = (const float*)d_in[1];
    const float* c0   = (const float*)d_in[2];
    const float* emb  = (const float*)d_in[3];
    const float* Wih  = (const float*)d_in[4];
    const float* Whh  = (const float*)d_in[5];
    const float* bih  = (const float*)d_in[6];
    const float* bhh  = (const float*)d_in[7];
    const float* Wout = (const float*)d_in[8];
    const float* bout = (const float*)d_in[9];
    float* out = (float*)d_out;

    int smemL = B * PADF * (int)sizeof(float);   // 98816 B
    int smemB = B * PADZ * (int)sizeof(float);   // 66048 B
    cudaFuncSetAttribute(logitsK, cudaFuncAttributeMaxDynamicSharedMemorySize, smemL);
    cudaFuncSetAttribute(baseK,   cudaFuncAttributeMaxDynamicSharedMemorySize, smemB);

    initK<<<64, 256>>>(h0, c0);
    constgateK<<<8192, 256>>>(h0, Wih, bih, bhh);   // 65536 warps: (b, R)
    baseK<<<VV / 64, 256, smemB>>>(h0, Wout, bout);

    for (int t = 0; t < TT; t++) {
        gatesK<<<2048, 256>>>(t, y0, emb, Wih, Whh);     // 16384 warps: (b, j)
        logitsK<<<VV / 64, 256, smemL>>>(t, y0, emb, Wout);
    }
    transposeK<<<dim3(VV / 32, TT / 32, B), dim3(32, 8)>>>(out);
}